// round 6
// baseline (speedup 1.0000x reference)
#include <cuda_runtime.h>
#include <cstdint>

typedef unsigned long long u64;

// ---- packed f32x2 helpers ----
__device__ __forceinline__ u64 ffma2(u64 a, u64 b, u64 c) {
    u64 d;
    asm("fma.rn.f32x2 %0, %1, %2, %3;" : "=l"(d) : "l"(a), "l"(b), "l"(c));
    return d;
}
__device__ __forceinline__ u64 addf2(u64 a, u64 b) {
    u64 d;
    asm("add.rn.f32x2 %0, %1, %2;" : "=l"(d) : "l"(a), "l"(b));
    return d;
}
__device__ __forceinline__ u64 pk(float x, float y) {
    u64 r; asm("mov.b64 %0, {%1, %2};" : "=l"(r) : "f"(x), "f"(y)); return r;
}
__device__ __forceinline__ float2 unpk(u64 v) {
    float2 r;
    asm("mov.b64 {%0, %1}, %2;" : "=f"(r.x), "=f"(r.y) : "l"(v));
    return r;
}

#define KD 25088
#define KH 4096
#define NROI 2048
#define NOUT 25
#define NCLS_ 21
#define HSPLIT 8
#define HPER (KH / HSPLIT)    // 512
#define KSEG 512
#define NSEG (KD / KSEG)      // 49
#define NRG 32                // 2048/64 rowgroups

// scratch (static device arrays)
__device__ __align__(16) float g_part[(size_t)HSPLIT * NOUT * KD];   // 20 MB
__device__ __align__(16) float g_M[NOUT * KD];                       // 2.5 MB
__device__ __align__(16) float g_p2[(size_t)NSEG * NRG * NOUT * 64]; // 10 MB
__device__ float g_biasf[NOUT];
__device__ float g_score[NROI];
__device__ __align__(16) float g_boxes[NROI * 4];

// ---------------- fused bias ----------------
__global__ void k_bias(const float* __restrict__ b1, const float* __restrict__ Wc,
                       const float* __restrict__ bc, const float* __restrict__ Wr,
                       const float* __restrict__ br) {
    int c = blockIdx.x;
    int tid = threadIdx.x;
    const float* p = (c < NCLS_) ? (Wc + (size_t)c * KH) : (Wr + (size_t)(c - NCLS_) * KH);
    float s = 0.f;
    for (int h = tid; h < KH; h += 256) s += b1[h] * p[h];
    __shared__ float red[256];
    red[tid] = s;
    __syncthreads();
    for (int o = 128; o > 0; o >>= 1) {
        if (tid < o) red[tid] += red[tid + o];
        __syncthreads();
    }
    if (tid == 0) g_biasf[c] = red[0] + ((c < NCLS_) ? bc[c] : br[c - NCLS_]);
}

// ---------------- k1: partial M[c,d] = sum_h P[c,h]*W1[h,d] ----------------
// 128 thr, thread owns 4 consecutive d. acc[25][2] = 100 regs.
// Inner: 2-h sub-iteration; rotating prefetch of the P broadcast (LDS.128) so the
// dependent FFMA2s of c are issued while m for c+1 is in flight. W rows for the
// next sub-iter prefetched during current compute (~600 cyc wall > 577 DRAM).
__global__ __launch_bounds__(128, 3) void k1_partial(const float* __restrict__ W1,
                                                     const float* __restrict__ Wc,
                                                     const float* __restrict__ Wr) {
    __shared__ __align__(16) u64 sPd[64][NOUT][2];   // [h-pair][c][h-parity], dup pairs
    int tid = threadIdx.x;
    int d = blockIdx.x * 512 + tid * 4;
    int hbase = blockIdx.y * HPER;

    u64 acc[NOUT][2];
#pragma unroll
    for (int c = 0; c < NOUT; c++) { acc[c][0] = 0ull; acc[c][1] = 0ull; }

    for (int ch = 0; ch < HPER / 128; ch++) {        // 4 chunks of 128 h
        int h0 = hbase + ch * 128;
        __syncthreads();
        for (int i = tid; i < 64 * NOUT; i += 128) {
            int c = i >> 6, j2 = i & 63;
            int h = h0 + 2 * j2;
            float v0, v1;
            if (c < NCLS_) { v0 = Wc[(size_t)c * KH + h]; v1 = Wc[(size_t)c * KH + h + 1]; }
            else { v0 = Wr[(size_t)(c - NCLS_) * KH + h]; v1 = Wr[(size_t)(c - NCLS_) * KH + h + 1]; }
            sPd[j2][c][0] = pk(v0, v0);
            sPd[j2][c][1] = pk(v1, v1);
        }
        __syncthreads();

        float4 cur0, cur1, nxt0, nxt1;
        cur0 = *reinterpret_cast<const float4*>(W1 + (size_t)h0 * KD + d);
        cur1 = *reinterpret_cast<const float4*>(W1 + (size_t)(h0 + 1) * KD + d);

        for (int j2 = 0; j2 < 64; j2++) {            // sub-iter = 2 h
            int hn = (j2 < 63) ? (h0 + 2 * j2 + 2) : hbase;   // dummy-safe at end
            nxt0 = *reinterpret_cast<const float4*>(W1 + (size_t)hn * KD + d);
            nxt1 = *reinterpret_cast<const float4*>(W1 + (size_t)(hn + 1) * KD + d);

            u64 w0a = pk(cur0.x, cur0.y), w0b = pk(cur0.z, cur0.w);
            u64 w1a = pk(cur1.x, cur1.y), w1b = pk(cur1.z, cur1.w);

            // rotating broadcast prefetch over c
            ulonglong2 m = *reinterpret_cast<const ulonglong2*>(&sPd[j2][0][0]);
#pragma unroll
            for (int c = 0; c < NOUT; c++) {
                ulonglong2 mn = m;
                if (c < NOUT - 1)
                    mn = *reinterpret_cast<const ulonglong2*>(&sPd[j2][c + 1][0]);
                acc[c][0] = ffma2(m.x, w0a, acc[c][0]);
                acc[c][1] = ffma2(m.x, w0b, acc[c][1]);
                acc[c][0] = ffma2(m.y, w1a, acc[c][0]);
                acc[c][1] = ffma2(m.y, w1b, acc[c][1]);
                m = mn;
            }
            cur0 = nxt0; cur1 = nxt1;
        }
    }
    float* op = g_part + (size_t)blockIdx.y * NOUT * KD + d;
#pragma unroll
    for (int c = 0; c < NOUT; c++) {
        ulonglong2 v; v.x = acc[c][0]; v.y = acc[c][1];
        *reinterpret_cast<ulonglong2*>(op + (size_t)c * KD) = v;
    }
}

// ---------------- reduce partials -> M ----------------
__global__ void k_reduce() {
    int i = blockIdx.x * 256 + threadIdx.x;   // < 313600 u64
    const u64* gp = reinterpret_cast<const u64*>(g_part);
    u64 s = gp[i];
#pragma unroll
    for (int p = 1; p < HSPLIT; p++) s = addf2(s, gp[(size_t)p * 313600 + i]);
    reinterpret_cast<u64*>(g_M)[i] = s;
}

// ---------------- k2_main: logits partials, k-major tile with XOR swizzle ----------------
// grid (NRG, NSEG), 128 thr = 4 warps; warp w owns kp-quarter of each 128-k chunk.
// Thread owns rows (2*lane, 2*lane+1). Rotating prefetch of the M broadcast and
// next-step f vectors: dependent LDS always in flight behind >=1 c-block of FFMA2.
#define K2SFK (64 * 64)          // u64 entries (128 k x 64 rows)
#define K2SM  (NOUT * 64)        // u64 entries
__global__ __launch_bounds__(128, 3) void k2_main(const float* __restrict__ feats) {
    __shared__ __align__(16) unsigned char smem_raw[(K2SFK + K2SM) * 8];  // 45.3 KB
    u64 (*sFk)[64] = reinterpret_cast<u64(*)[64]>(smem_raw);
    u64 (*sM)[64] = reinterpret_cast<u64(*)[64]>(smem_raw + K2SFK * 8);
    float* sRed = reinterpret_cast<float*>(smem_raw);    // aliased after compute

    int tid = threadIdx.x, w = tid >> 5, lane = tid & 31;
    int rg = blockIdx.x, ks = blockIdx.y;
    int rowbase = rg * 64;
    int kbase = ks * KSEG;
    int srow = tid >> 4;        // staging: base row 0..7
    int skl = tid & 15;         // staging: k-lane

    u64 acc[NOUT][2];
#pragma unroll
    for (int c = 0; c < NOUT; c++) { acc[c][0] = 0ull; acc[c][1] = 0ull; }

    for (int chunk = 0; chunk < 4; chunk++) {            // 4 x 128 k
        int k0 = kbase + chunk * 128;
        __syncthreads();
#pragma unroll
        for (int half = 0; half < 2; half++) {
            float4 fv[8];
#pragma unroll
            for (int p = 0; p < 8; p++) {
                int pass = half * 8 + p;
                int row = srow + 8 * (pass & 7);
                int kq = skl + 16 * (pass >> 3);
                fv[p] = *reinterpret_cast<const float4*>(feats + (size_t)(rowbase + row) * KD + k0 + kq * 4);
            }
#pragma unroll
            for (int p = 0; p < 8; p++) {
                int pass = half * 8 + p;
                int row = srow + 8 * (pass & 7);
                int kq = skl + 16 * (pass >> 3);
                int kp = kq * 2;
                sFk[kp][row ^ ((2 * kp) & 63)]         = pk(fv[p].x, fv[p].y);
                sFk[kp + 1][row ^ ((2 * kp + 2) & 63)] = pk(fv[p].z, fv[p].w);
            }
        }
        for (int i = tid; i < NOUT * 32; i += 128) {
            int c = i >> 5, kq = i & 31;
            float4 mv = *reinterpret_cast<const float4*>(g_M + (size_t)c * KD + k0 + kq * 4);
            ulonglong2 e; e.x = pk(mv.x, mv.y); e.y = pk(mv.z, mv.w);
            *reinterpret_cast<ulonglong2*>(&sM[c][kq * 2]) = e;
        }
        __syncthreads();

        // compute: warp's 16 kp, 2 per step; f prefetched one step ahead
        int kp0 = w * 16;
        ulonglong2 f0 = *reinterpret_cast<const ulonglong2*>(&sFk[kp0][(2 * lane) ^ ((2 * kp0) & 63)]);
        ulonglong2 f1 = *reinterpret_cast<const ulonglong2*>(&sFk[kp0 + 1][(2 * lane) ^ ((2 * kp0 + 2) & 63)]);
#pragma unroll
        for (int kk = 0; kk < 16; kk += 2) {
            int kp = w * 16 + kk;
            ulonglong2 f0n = f0, f1n = f1;
            if (kk < 14) {
                int kpn = kp + 2;
                f0n = *reinterpret_cast<const ulonglong2*>(&sFk[kpn][(2 * lane) ^ ((2 * kpn) & 63)]);
                f1n = *reinterpret_cast<const ulonglong2*>(&sFk[kpn + 1][(2 * lane) ^ ((2 * kpn + 2) & 63)]);
            }
            // rotating M broadcast prefetch over c
            ulonglong2 m = *reinterpret_cast<const ulonglong2*>(&sM[0][kp]);
#pragma unroll
            for (int c = 0; c < NOUT; c++) {
                ulonglong2 mn = m;
                if (c < NOUT - 1)
                    mn = *reinterpret_cast<const ulonglong2*>(&sM[c + 1][kp]);
                acc[c][0] = ffma2(f0.x, m.x, acc[c][0]);
                acc[c][1] = ffma2(f0.y, m.x, acc[c][1]);
                acc[c][0] = ffma2(f1.x, m.y, acc[c][0]);
                acc[c][1] = ffma2(f1.y, m.y, acc[c][1]);
                m = mn;
            }
            f0 = f0n; f1 = f1n;
        }
    }

    // cross-warp reduce via shared (aliases sFk; safe after sync)
    __syncthreads();
#pragma unroll
    for (int c = 0; c < NOUT; c++) {
        float2 a = unpk(acc[c][0]);
        float2 b = unpk(acc[c][1]);
        sRed[w * 1600 + c * 64 + 2 * lane]     = a.x + a.y;
        sRed[w * 1600 + c * 64 + 2 * lane + 1] = b.x + b.y;
    }
    __syncthreads();
    float* outp = g_p2 + (size_t)(ks * NRG + rg) * (NOUT * 64);
    for (int i = tid; i < 1600; i += 128) {
        float v = sRed[i] + sRed[1600 + i] + sRed[3200 + i] + sRed[4800 + i];
        outp[i] = v;
    }
}

// ---------------- k2r: sum seg partials + softmax/argmax/box decode ----------------
__global__ __launch_bounds__(256) void k2r(const float* __restrict__ props) {
    int tid = threadIdx.x, lane = tid & 31;
    int row = blockIdx.x * 8 + (tid >> 5);
    int rg = row >> 6, rowin = row & 63;

    float t[NOUT];
#pragma unroll
    for (int c = 0; c < NOUT; c++) t[c] = 0.f;
#pragma unroll
    for (int half = 0; half < 2; half++) {
        int s = lane + half * 32;
        if (s < NSEG) {
            const float* base = g_p2 + (size_t)(s * NRG + rg) * (NOUT * 64) + rowin;
#pragma unroll
            for (int c = 0; c < NOUT; c++) t[c] += base[c * 64];
        }
    }
#pragma unroll
    for (int c = 0; c < NOUT; c++) {
#pragma unroll
        for (int o = 16; o > 0; o >>= 1) t[c] += __shfl_xor_sync(0xffffffffu, t[c], o);
    }

    if (lane == 0) {
#pragma unroll
        for (int c = 0; c < NOUT; c++) t[c] += g_biasf[c];
        float m = t[0]; int idx = 0;
#pragma unroll
        for (int c = 1; c < NCLS_; c++) { if (t[c] > m) { m = t[c]; idx = c; } }
        float ssum = 0.f;
#pragma unroll
        for (int c = 0; c < NCLS_; c++) ssum += expf(t[c] - m);
        float score = 1.f / ssum;
        bool valid = (idx != 0) && (score >= 0.01f);
        float p0 = props[row * 4 + 0], p1 = props[row * 4 + 1];
        float p2 = props[row * 4 + 2], p3 = props[row * 4 + 3];
        g_score[row] = valid ? score : 0.f;
        g_boxes[row * 4 + 0] = p0 + p2 * t[NCLS_ + 0];
        g_boxes[row * 4 + 1] = p1 + p3 * t[NCLS_ + 1];
        g_boxes[row * 4 + 2] = p2 * expf(t[NCLS_ + 2]);
        g_boxes[row * 4 + 3] = p3 * expf(t[NCLS_ + 3]);
    }
}

// ---------------- k3: exact greedy NMS per batch ----------------
__global__ __launch_bounds__(512) void k3_nms(float* __restrict__ out) {
    __shared__ float sraw[512];
    __shared__ float ss[512], sx0[512], sy0[512], sx1[512], sy1[512], sa[512];
    __shared__ short sord[512];
    __shared__ unsigned char ssup[512];

    int b = blockIdx.x, t = threadIdx.x;
    int gi = b * 512 + t;
    float sc = g_score[gi];
    sraw[t] = sc;
    float bx = g_boxes[gi * 4 + 0], by = g_boxes[gi * 4 + 1];
    float bw = g_boxes[gi * 4 + 2], bh = g_boxes[gi * 4 + 3];
    __syncthreads();

    int r = 0;
    for (int i = 0; i < 512; i++) {
        float si = sraw[i];
        r += (si > sc) || (si == sc && i < t);
    }

    float x0 = fminf(fmaxf(bx, 0.f), 599.f);
    float y0 = fminf(fmaxf(by, 0.f), 599.f);
    float x1 = fminf(fmaxf(bx + bw - 1.f, 0.f), 599.f);
    float y1 = fminf(fmaxf(by + bh - 1.f, 0.f), 599.f);
    float area = fmaxf(x1 - x0 + 1.f, 0.f) * fmaxf(y1 - y0 + 1.f, 0.f);

    ss[r] = sc; sx0[r] = x0; sy0[r] = y0; sx1[r] = x1; sy1[r] = y1; sa[r] = area;
    sord[r] = (short)t;
    ssup[t] = 0;
    __syncthreads();

    for (int i = 0; i < 512; i++) {
        bool alive = (!ssup[i]) && (ss[i] > 0.f);
        if (alive && t != i) {
            float ix0 = fmaxf(sx0[i], sx0[t]);
            float iy0 = fmaxf(sy0[i], sy0[t]);
            float ix1 = fminf(sx1[i], sx1[t]);
            float iy1 = fminf(sy1[i], sy1[t]);
            float inter = fmaxf(ix1 - ix0 + 1.f, 0.f) * fmaxf(iy1 - iy0 + 1.f, 0.f);
            float iou = inter / (sa[i] + sa[t] - inter + 1e-9f);
            if (iou > 0.5f) ssup[t] = 1;
        }
        __syncthreads();
    }

    bool keep = (!ssup[t]) && (ss[t] > 0.f);
    int orig = sord[t];
    int go = b * 512 + orig;

    out[go] = keep ? ss[t] : 0.f;

    float obx = g_boxes[go * 4 + 0], oby = g_boxes[go * 4 + 1];
    float obw = g_boxes[go * 4 + 2], obh = g_boxes[go * 4 + 3];
    float* ob = out + NROI + (size_t)go * 4;
    if (keep) {
        ob[0] = obx; ob[1] = oby;
        ob[2] = obx + obw - 1.f;
        ob[3] = oby + obh - 1.f;
    } else {
        ob[0] = 0.f; ob[1] = 0.f; ob[2] = -1.f; ob[3] = -1.f;
    }
}

extern "C" void kernel_launch(void* const* d_in, const int* in_sizes, int n_in,
                              void* d_out, int out_size) {
    (void)in_sizes; (void)n_in; (void)out_size;
    const float* rois  = (const float*)d_in[0];
    const float* props = (const float*)d_in[1];
    const float* W1    = (const float*)d_in[2];
    const float* b1    = (const float*)d_in[3];
    const float* Wc    = (const float*)d_in[4];
    const float* bc    = (const float*)d_in[5];
    const float* Wr    = (const float*)d_in[6];
    const float* br    = (const float*)d_in[7];
    float* out = (float*)d_out;

    k_bias<<<NOUT, 256>>>(b1, Wc, bc, Wr, br);
    dim3 g1(KD / 512, HSPLIT);                 // (49, 8) = 392 blocks, one wave
    k1_partial<<<g1, 128>>>(W1, Wc, Wr);
    k_reduce<<<313600 / 256, 256>>>();
    dim3 g2(NRG, NSEG);                        // (32, 49)
    k2_main<<<g2, 128>>>(rois);
    k2r<<<NROI / 8, 256>>>(props);
    k3_nms<<<4, 512>>>(out);
}

// round 7
// speedup vs baseline: 1.0178x; 1.0178x over previous
#include <cuda_runtime.h>
#include <cstdint>

typedef unsigned long long u64;

// ---- packed f32x2 helpers ----
__device__ __forceinline__ u64 ffma2(u64 a, u64 b, u64 c) {
    u64 d;
    asm("fma.rn.f32x2 %0, %1, %2, %3;" : "=l"(d) : "l"(a), "l"(b), "l"(c));
    return d;
}
__device__ __forceinline__ u64 addf2(u64 a, u64 b) {
    u64 d;
    asm("add.rn.f32x2 %0, %1, %2;" : "=l"(d) : "l"(a), "l"(b));
    return d;
}
__device__ __forceinline__ u64 pk(float x, float y) {
    u64 r; asm("mov.b64 %0, {%1, %2};" : "=l"(r) : "f"(x), "f"(y)); return r;
}
__device__ __forceinline__ float2 unpk(u64 v) {
    float2 r;
    asm("mov.b64 {%0, %1}, %2;" : "=f"(r.x), "=f"(r.y) : "l"(v));
    return r;
}

#define KD 25088
#define KH 4096
#define NROI 2048
#define NOUT 25
#define NCLS_ 21
#define HSPLIT 16
#define HPER (KH / HSPLIT)    // 256
#define CH 16                 // k1 h per chunk
#define KSEG 512
#define NSEG (KD / KSEG)      // 49
#define NRG 32                // 2048/64 rowgroups

// scratch (static device arrays)
__device__ __align__(16) float g_part[(size_t)HSPLIT * NOUT * KD];   // 40.1 MB
__device__ __align__(16) float g_M[NOUT * KD];                       // 2.5 MB
__device__ __align__(16) float g_p2[(size_t)NSEG * NRG * NOUT * 64]; // 10 MB
__device__ float g_biasf[NOUT];
__device__ float g_score[NROI];
__device__ __align__(16) float g_boxes[NROI * 4];

// ---------------- fused bias ----------------
__global__ void k_bias(const float* __restrict__ b1, const float* __restrict__ Wc,
                       const float* __restrict__ bc, const float* __restrict__ Wr,
                       const float* __restrict__ br) {
    int c = blockIdx.x;
    int tid = threadIdx.x;
    const float* p = (c < NCLS_) ? (Wc + (size_t)c * KH) : (Wr + (size_t)(c - NCLS_) * KH);
    float s = 0.f;
    for (int h = tid; h < KH; h += 256) s += b1[h] * p[h];
    __shared__ float red[256];
    red[tid] = s;
    __syncthreads();
    for (int o = 128; o > 0; o >>= 1) {
        if (tid < o) red[tid] += red[tid + o];
        __syncthreads();
    }
    if (tid == 0) g_biasf[c] = red[0] + ((c < NCLS_) ? bc[c] : br[c - NCLS_]);
}

// ---------------- k1: partial M[c,d] = sum_h P[c,h]*W1[h,d] ----------------
// 256 thr = 8 warps: wq = w&3 -> d-quarter (128 d), chalf = w>>2 -> c-half (13 c).
// Thread owns 4 d -> acc[13][2]. W tile sW4[h][dquad]: staging AND compute both
// h-fixed row-contiguous => conflict-free. P dup-pairs: 1-phase broadcasts.
// Next chunk's W held in fv[8] registers across compute (MLP 8 LDG.128/thread).
__global__ __launch_bounds__(256, 2) void k1_partial(const float* __restrict__ W1,
                                                     const float* __restrict__ Wc,
                                                     const float* __restrict__ Wr) {
    __shared__ __align__(16) float4 sW4[CH][128];       // 32 KB
    __shared__ __align__(16) ulonglong2 sPd[CH / 2][NOUT]; // 3.2 KB dup pairs
    int tid = threadIdx.x;
    int w = tid >> 5, lane = tid & 31;
    int wq = w & 3, chalf = w >> 2;
    int cb = chalf * 12;
    int db = blockIdx.x * 512;
    int hbase = blockIdx.y * HPER;
    int dql = tid & 31;

    u64 acc[13][2];
#pragma unroll
    for (int i = 0; i < 13; i++) { acc[i][0] = 0ull; acc[i][1] = 0ull; }

    // prologue: stage chunk 0
    {
        float4 fv[8];
#pragma unroll
        for (int q = 0; q < 8; q++) {
            int h = w + 8 * (q & 1);
            int dq = dql + 32 * (q >> 1);
            fv[q] = *reinterpret_cast<const float4*>(W1 + (size_t)(hbase + h) * KD + db + dq * 4);
        }
#pragma unroll
        for (int q = 0; q < 8; q++)
            sW4[w + 8 * (q & 1)][dql + 32 * (q >> 1)] = fv[q];
        if (tid < 8 * NOUT) {
            int c = tid >> 3, j2 = tid & 7;
            const float* ps = (c < NCLS_) ? (Wc + (size_t)c * KH) : (Wr + (size_t)(c - NCLS_) * KH);
            float v0 = ps[hbase + 2 * j2], v1 = ps[hbase + 2 * j2 + 1];
            ulonglong2 e; e.x = pk(v0, v0); e.y = pk(v1, v1);
            sPd[j2][c] = e;
        }
        __syncthreads();
    }

    for (int ch = 0; ch < HPER / CH; ch++) {
        bool pf = (ch < HPER / CH - 1);
        int h0n = hbase + (ch + 1) * CH;
        float4 fv[8];
        if (pf) {
#pragma unroll
            for (int q = 0; q < 8; q++) {
                int h = w + 8 * (q & 1);
                int dq = dql + 32 * (q >> 1);
                fv[q] = *reinterpret_cast<const float4*>(W1 + (size_t)(h0n + h) * KD + db + dq * 4);
            }
        }
        // compute current chunk from smem
#pragma unroll
        for (int j2 = 0; j2 < CH / 2; j2++) {
            ulonglong2 fa = *reinterpret_cast<const ulonglong2*>(&sW4[2 * j2][wq * 32 + lane]);
            ulonglong2 fb = *reinterpret_cast<const ulonglong2*>(&sW4[2 * j2 + 1][wq * 32 + lane]);
#pragma unroll
            for (int i = 0; i < 13; i++) {
                ulonglong2 m = sPd[j2][cb + i];     // broadcast LDS.128
                acc[i][0] = ffma2(m.x, fa.x, acc[i][0]);
                acc[i][1] = ffma2(m.x, fa.y, acc[i][1]);
                acc[i][0] = ffma2(m.y, fb.x, acc[i][0]);
                acc[i][1] = ffma2(m.y, fb.y, acc[i][1]);
            }
        }
        __syncthreads();
        if (pf) {
#pragma unroll
            for (int q = 0; q < 8; q++)
                sW4[w + 8 * (q & 1)][dql + 32 * (q >> 1)] = fv[q];
            if (tid < 8 * NOUT) {
                int c = tid >> 3, j2 = tid & 7;
                const float* ps = (c < NCLS_) ? (Wc + (size_t)c * KH) : (Wr + (size_t)(c - NCLS_) * KH);
                float v0 = ps[h0n + 2 * j2], v1 = ps[h0n + 2 * j2 + 1];
                ulonglong2 e; e.x = pk(v0, v0); e.y = pk(v1, v1);
                sPd[j2][c] = e;
            }
            __syncthreads();
        }
    }

    int d = db + wq * 128 + lane * 4;
    int i0 = (chalf == 1) ? 1 : 0;      // half1 skips its c=12 duplicate
    float* gp = g_part + (size_t)blockIdx.y * (NOUT * KD);
#pragma unroll
    for (int i = 0; i < 13; i++) {
        if (i >= i0) {
            ulonglong2 v; v.x = acc[i][0]; v.y = acc[i][1];
            *reinterpret_cast<ulonglong2*>(gp + (size_t)(cb + i) * KD + d) = v;
        }
    }
}

// ---------------- reduce partials -> M ----------------
__global__ void k_reduce() {
    int i = blockIdx.x * 256 + threadIdx.x;   // < 313600 u64
    const u64* gp = reinterpret_cast<const u64*>(g_part);
    u64 s = gp[i];
#pragma unroll
    for (int p = 1; p < HSPLIT; p++) s = addf2(s, gp[(size_t)p * 313600 + i]);
    reinterpret_cast<u64*>(g_M)[i] = s;
}

// ---------------- k2_main: logits partials ----------------
// 256 thr = 8 warps: wq = w&3 -> kq-quarter, chalf = w>>2 -> c-half (13 c).
// Thread owns rows (lane, lane+32) -> acc[13][2]. Tile sF4[kq][row ^ (kq&7)]:
// staging STS.128 and compute LDS.128 both at the 4-phase floor. M broadcast.
__global__ __launch_bounds__(256, 2) void k2_main(const float* __restrict__ feats) {
    __shared__ __align__(16) float4 sF4[32][64];    // 32 KB
    __shared__ __align__(16) float4 sM4[NOUT][32];  // 12.8 KB
    float* sRed = reinterpret_cast<float*>(sF4);    // aliased after compute (26.6 KB)

    int tid = threadIdx.x;
    int w = tid >> 5, lane = tid & 31;
    int wq = w & 3, chalf = w >> 2;
    int cb = chalf * 12;
    int rowbase = blockIdx.x * 64;
    int kbase = blockIdx.y * KSEG;
    int skq = tid & 31;

    u64 acc[13][2];
#pragma unroll
    for (int i = 0; i < 13; i++) { acc[i][0] = 0ull; acc[i][1] = 0ull; }

    // prologue: stage chunk 0
    {
        float4 fv[8];
#pragma unroll
        for (int p = 0; p < 8; p++)
            fv[p] = *reinterpret_cast<const float4*>(feats + (size_t)(rowbase + w + 8 * p) * KD + kbase + skq * 4);
#pragma unroll
        for (int p = 0; p < 8; p++)
            sF4[skq][(w + 8 * p) ^ (skq & 7)] = fv[p];
        for (int i = tid; i < NOUT * 32; i += 256) {
            int c = i >> 5, kq = i & 31;
            sM4[c][kq] = *reinterpret_cast<const float4*>(g_M + (size_t)c * KD + kbase + kq * 4);
        }
        __syncthreads();
    }

    for (int chunk = 0; chunk < 4; chunk++) {
        bool pf = (chunk < 3);
        int k0n = kbase + (chunk + 1) * 128;
        float4 fv[8];
        if (pf) {
#pragma unroll
            for (int p = 0; p < 8; p++)
                fv[p] = *reinterpret_cast<const float4*>(feats + (size_t)(rowbase + w + 8 * p) * KD + k0n + skq * 4);
        }
#pragma unroll
        for (int kk = 0; kk < 8; kk++) {
            int kq = wq * 8 + kk;
            ulonglong2 fa = *reinterpret_cast<const ulonglong2*>(&sF4[kq][lane ^ (kq & 7)]);
            ulonglong2 fb = *reinterpret_cast<const ulonglong2*>(&sF4[kq][(lane + 32) ^ (kq & 7)]);
#pragma unroll
            for (int i = 0; i < 13; i++) {
                ulonglong2 m = *reinterpret_cast<const ulonglong2*>(&sM4[cb + i][kq]);  // broadcast
                acc[i][0] = ffma2(fa.x, m.x, acc[i][0]);
                acc[i][0] = ffma2(fa.y, m.y, acc[i][0]);
                acc[i][1] = ffma2(fb.x, m.x, acc[i][1]);
                acc[i][1] = ffma2(fb.y, m.y, acc[i][1]);
            }
        }
        __syncthreads();
        if (pf) {
#pragma unroll
            for (int p = 0; p < 8; p++)
                sF4[skq][(w + 8 * p) ^ (skq & 7)] = fv[p];
            for (int i = tid; i < NOUT * 32; i += 256) {
                int c = i >> 5, kq = i & 31;
                sM4[c][kq] = *reinterpret_cast<const float4*>(g_M + (size_t)c * KD + k0n + kq * 4);
            }
            __syncthreads();
        }
    }

    // reduction across kq-quarters (warps within each c-half)
    __syncthreads();
#pragma unroll
    for (int i = 0; i < 13; i++) {
        float2 a = unpk(acc[i][0]);
        float2 b = unpk(acc[i][1]);
        sRed[w * 832 + i * 64 + lane]      = a.x + a.y;   // row = lane
        sRed[w * 832 + i * 64 + 32 + lane] = b.x + b.y;   // row = lane+32
    }
    __syncthreads();
    float* outp = g_p2 + (size_t)(blockIdx.y * NRG + blockIdx.x) * (NOUT * 64);
    for (int idx = tid; idx < NOUT * 64; idx += 256) {
        int c = idx >> 6, r = idx & 63;
        int half = (c >= 13) ? 1 : 0;
        int i = half ? (c - 12) : c;
        float v = 0.f;
#pragma unroll
        for (int q = 0; q < 4; q++)
            v += sRed[(half * 4 + q) * 832 + i * 64 + r];
        outp[idx] = v;
    }
}

// ---------------- k2r: sum seg partials + softmax/argmax/box decode ----------------
__global__ __launch_bounds__(256) void k2r(const float* __restrict__ props) {
    int tid = threadIdx.x, lane = tid & 31;
    int row = blockIdx.x * 8 + (tid >> 5);
    int rg = row >> 6, rowin = row & 63;

    float t[NOUT];
#pragma unroll
    for (int c = 0; c < NOUT; c++) t[c] = 0.f;
#pragma unroll
    for (int half = 0; half < 2; half++) {
        int s = lane + half * 32;
        if (s < NSEG) {
            const float* base = g_p2 + (size_t)(s * NRG + rg) * (NOUT * 64) + rowin;
#pragma unroll
            for (int c = 0; c < NOUT; c++) t[c] += base[c * 64];
        }
    }
#pragma unroll
    for (int c = 0; c < NOUT; c++) {
#pragma unroll
        for (int o = 16; o > 0; o >>= 1) t[c] += __shfl_xor_sync(0xffffffffu, t[c], o);
    }

    if (lane == 0) {
#pragma unroll
        for (int c = 0; c < NOUT; c++) t[c] += g_biasf[c];
        float m = t[0]; int idx = 0;
#pragma unroll
        for (int c = 1; c < NCLS_; c++) { if (t[c] > m) { m = t[c]; idx = c; } }
        float ssum = 0.f;
#pragma unroll
        for (int c = 0; c < NCLS_; c++) ssum += expf(t[c] - m);
        float score = 1.f / ssum;
        bool valid = (idx != 0) && (score >= 0.01f);
        float p0 = props[row * 4 + 0], p1 = props[row * 4 + 1];
        float p2 = props[row * 4 + 2], p3 = props[row * 4 + 3];
        g_score[row] = valid ? score : 0.f;
        g_boxes[row * 4 + 0] = p0 + p2 * t[NCLS_ + 0];
        g_boxes[row * 4 + 1] = p1 + p3 * t[NCLS_ + 1];
        g_boxes[row * 4 + 2] = p2 * expf(t[NCLS_ + 2]);
        g_boxes[row * 4 + 3] = p3 * expf(t[NCLS_ + 3]);
    }
}

// ---------------- k3: exact greedy NMS per batch ----------------
__global__ __launch_bounds__(512) void k3_nms(float* __restrict__ out) {
    __shared__ float sraw[512];
    __shared__ float ss[512], sx0[512], sy0[512], sx1[512], sy1[512], sa[512];
    __shared__ short sord[512];
    __shared__ unsigned char ssup[512];

    int b = blockIdx.x, t = threadIdx.x;
    int gi = b * 512 + t;
    float sc = g_score[gi];
    sraw[t] = sc;
    float bx = g_boxes[gi * 4 + 0], by = g_boxes[gi * 4 + 1];
    float bw = g_boxes[gi * 4 + 2], bh = g_boxes[gi * 4 + 3];
    __syncthreads();

    int r = 0;
    for (int i = 0; i < 512; i++) {
        float si = sraw[i];
        r += (si > sc) || (si == sc && i < t);
    }

    float x0 = fminf(fmaxf(bx, 0.f), 599.f);
    float y0 = fminf(fmaxf(by, 0.f), 599.f);
    float x1 = fminf(fmaxf(bx + bw - 1.f, 0.f), 599.f);
    float y1 = fminf(fmaxf(by + bh - 1.f, 0.f), 599.f);
    float area = fmaxf(x1 - x0 + 1.f, 0.f) * fmaxf(y1 - y0 + 1.f, 0.f);

    ss[r] = sc; sx0[r] = x0; sy0[r] = y0; sx1[r] = x1; sy1[r] = y1; sa[r] = area;
    sord[r] = (short)t;
    ssup[t] = 0;
    __syncthreads();

    for (int i = 0; i < 512; i++) {
        bool alive = (!ssup[i]) && (ss[i] > 0.f);
        if (alive && t != i) {
            float ix0 = fmaxf(sx0[i], sx0[t]);
            float iy0 = fmaxf(sy0[i], sy0[t]);
            float ix1 = fminf(sx1[i], sx1[t]);
            float iy1 = fminf(sy1[i], sy1[t]);
            float inter = fmaxf(ix1 - ix0 + 1.f, 0.f) * fmaxf(iy1 - iy0 + 1.f, 0.f);
            float iou = inter / (sa[i] + sa[t] - inter + 1e-9f);
            if (iou > 0.5f) ssup[t] = 1;
        }
        __syncthreads();
    }

    bool keep = (!ssup[t]) && (ss[t] > 0.f);
    int orig = sord[t];
    int go = b * 512 + orig;

    out[go] = keep ? ss[t] : 0.f;

    float obx = g_boxes[go * 4 + 0], oby = g_boxes[go * 4 + 1];
    float obw = g_boxes[go * 4 + 2], obh = g_boxes[go * 4 + 3];
    float* ob = out + NROI + (size_t)go * 4;
    if (keep) {
        ob[0] = obx; ob[1] = oby;
        ob[2] = obx + obw - 1.f;
        ob[3] = oby + obh - 1.f;
    } else {
        ob[0] = 0.f; ob[1] = 0.f; ob[2] = -1.f; ob[3] = -1.f;
    }
}

extern "C" void kernel_launch(void* const* d_in, const int* in_sizes, int n_in,
                              void* d_out, int out_size) {
    (void)in_sizes; (void)n_in; (void)out_size;
    const float* rois  = (const float*)d_in[0];
    const float* props = (const float*)d_in[1];
    const float* W1    = (const float*)d_in[2];
    const float* b1    = (const float*)d_in[3];
    const float* Wc    = (const float*)d_in[4];
    const float* bc    = (const float*)d_in[5];
    const float* Wr    = (const float*)d_in[6];
    const float* br    = (const float*)d_in[7];
    float* out = (float*)d_out;

    k_bias<<<NOUT, 256>>>(b1, Wc, bc, Wr, br);
    dim3 g1(KD / 512, HSPLIT);                 // (49, 16)
    k1_partial<<<g1, 256>>>(W1, Wc, Wr);
    k_reduce<<<313600 / 256, 256>>>();
    dim3 g2(NRG, NSEG);                        // (32, 49)
    k2_main<<<g2, 256>>>(rois);
    k2r<<<NROI / 8, 256>>>(props);
    k3_nms<<<4, 512>>>(out);
}